// round 4
// baseline (speedup 1.0000x reference)
#include <cuda_runtime.h>

// 3x3 median blur, zero padding, fp32 NCHW (8,3,512,512).
// 2 rows x 8 cols per thread; shared vertical pair-sort per column across the
// two output rows; rolling 3-column triple window + early float4 stores to
// keep register pressure under the 64-reg / 8-blocks-per-SM occupancy target.

__device__ __forceinline__ float med3(float a, float b, float c) {
    return fmaxf(fminf(a, b), fminf(fmaxf(a, b), c));
}
__device__ __forceinline__ float max3(float a, float b, float c) {
    return fmaxf(fmaxf(a, b), c);
}
__device__ __forceinline__ float min3(float a, float b, float c) {
    return fminf(fminf(a, b), c);
}

template <bool CHECK_Y>
__device__ __forceinline__ void tile2x8(const float* __restrict__ p,
                                        float* __restrict__ outp,
                                        int x0, int y0) {
    // Input window: rows y0-1 .. y0+2, cols x0-1 .. x0+8 (zero-padded).
    float v[4][10];
    const bool lx = (x0 > 0);
    const bool rx = (x0 + 8 < 512);

    #pragma unroll
    for (int i = 0; i < 4; ++i) {
        const int yy = y0 - 1 + i;
        if (CHECK_Y && (unsigned)yy >= 512u) {
            #pragma unroll
            for (int j = 0; j < 10; ++j) v[i][j] = 0.0f;
        } else {
            const float* __restrict__ row = p + yy * 512;
            const float4 a = *reinterpret_cast<const float4*>(row + x0);
            const float4 b = *reinterpret_cast<const float4*>(row + x0 + 4);
            v[i][1] = a.x; v[i][2] = a.y; v[i][3] = a.z; v[i][4] = a.w;
            v[i][5] = b.x; v[i][6] = b.y; v[i][7] = b.z; v[i][8] = b.w;
            v[i][0] = lx ? row[x0 - 1] : 0.0f;
            v[i][9] = rx ? row[x0 + 8] : 0.0f;
        }
    }

    float* __restrict__ rowA = outp + y0 * 512 + x0;
    float* __restrict__ rowB = rowA + 512;

    // Rolling per-column sorted triples for windows A (rows 0-2) and B (rows 1-3),
    // sharing the middle-pair compare-exchange. Only 3 columns live at a time.
    float alo[3], ami[3], ahi[3];
    float blo[3], bmi[3], bhi[3];
    float oA[4], oB[4];

    #pragma unroll
    for (int j = 0; j < 10; ++j) {
        const int s = j % 3;
        const float mn = fminf(v[1][j], v[2][j]);
        const float mx = fmaxf(v[1][j], v[2][j]);
        {   // window A: insert top row into sorted (mn, mx)
            const float a = v[0][j];
            const float u = fmaxf(a, mn);
            alo[s] = fminf(a, mn);
            ami[s] = fminf(u, mx);
            ahi[s] = fmaxf(u, mx);
        }
        {   // window B: insert bottom row into sorted (mn, mx)
            const float d = v[3][j];
            const float w = fmaxf(d, mn);
            blo[s] = fminf(d, mn);
            bmi[s] = fminf(w, mx);
            bhi[s] = fmaxf(w, mx);
        }
        if (j >= 2) {
            const int k = j - 2;   // output pixel index 0..7
            oA[k % 4] = med3(max3(alo[0], alo[1], alo[2]),
                             med3(ami[0], ami[1], ami[2]),
                             min3(ahi[0], ahi[1], ahi[2]));
            oB[k % 4] = med3(max3(blo[0], blo[1], blo[2]),
                             med3(bmi[0], bmi[1], bmi[2]),
                             min3(bhi[0], bhi[1], bhi[2]));
            if ((k % 4) == 3) {   // flush 4 finished outputs per row
                const int off = k - 3;
                *reinterpret_cast<float4*>(rowA + off) =
                    make_float4(oA[0], oA[1], oA[2], oA[3]);
                *reinterpret_cast<float4*>(rowB + off) =
                    make_float4(oB[0], oB[1], oB[2], oB[3]);
            }
        }
    }
}

__global__ __launch_bounds__(128, 8)
void MedianBlur_34505767256654_kernel(const float* __restrict__ in,
                                      float* __restrict__ out) {
    const int x0 = (blockIdx.x * 32 + threadIdx.x) * 8;   // 8 cols per thread
    const int y0 = (blockIdx.y * 4 + threadIdx.y) * 2;    // 2 rows per thread
    const int base = blockIdx.z * (512 * 512);            // 24 planes

    const float* __restrict__ p = in + base;
    float* __restrict__ o = out + base;

    // Only the top and bottom y-blocks touch the vertical border.
    if (blockIdx.y != 0 && blockIdx.y != 63) {
        tile2x8<false>(p, o, x0, y0);
    } else {
        tile2x8<true>(p, o, x0, y0);
    }
}

extern "C" void kernel_launch(void* const* d_in, const int* in_sizes, int n_in,
                              void* d_out, int out_size) {
    (void)in_sizes; (void)n_in; (void)out_size;
    const float* x = (const float*)d_in[0];
    float* out = (float*)d_out;

    dim3 block(32, 4, 1);                    // 128 threads, tile 256x8 per block
    dim3 grid(512 / 256, 512 / 8, 24);       // (2, 64, 24)
    MedianBlur_34505767256654_kernel<<<grid, block>>>(x, out);
}

// round 5
// speedup vs baseline: 1.1544x; 1.1544x over previous
#include <cuda_runtime.h>

// 3x3 median blur, zero padding, fp32 NCHW (8,3,512,512).
// 2 rows x 4 cols per thread (8 px): shared vertical pair-sort per column
// across the two output rows (10 ops/col), med3(max3,med3,min3) merge
// (12 ops/px) -> 19.5 min/max ops + 1.5 loads per pixel.
// Straight-line unrolled body (max ILP) + 256-thread blocks at <=51 regs
// for ~62% occupancy: optimize warps*ILP jointly (R4 lesson).

__device__ __forceinline__ float med3(float a, float b, float c) {
    return fmaxf(fminf(a, b), fminf(fmaxf(a, b), c));
}
__device__ __forceinline__ float max3(float a, float b, float c) {
    return fmaxf(fmaxf(a, b), c);
}
__device__ __forceinline__ float min3(float a, float b, float c) {
    return fminf(fminf(a, b), c);
}

template <bool CHECK_Y>
__device__ __forceinline__ void tile2x4(const float* __restrict__ p,
                                        float* __restrict__ outp,
                                        int x0, int y0) {
    // Input window: rows y0-1 .. y0+2, cols x0-1 .. x0+4 (zero-padded).
    float v[4][6];
    const bool lx = (x0 > 0);
    const bool rx = (x0 + 4 < 512);

    #pragma unroll
    for (int i = 0; i < 4; ++i) {
        const int yy = y0 - 1 + i;
        if (CHECK_Y && (unsigned)yy >= 512u) {
            #pragma unroll
            for (int j = 0; j < 6; ++j) v[i][j] = 0.0f;
        } else {
            const float* __restrict__ row = p + yy * 512;
            const float4 a = *reinterpret_cast<const float4*>(row + x0);
            v[i][1] = a.x; v[i][2] = a.y; v[i][3] = a.z; v[i][4] = a.w;
            v[i][0] = lx ? row[x0 - 1] : 0.0f;
            v[i][5] = rx ? row[x0 + 4] : 0.0f;
        }
    }

    // Per column: sorted triples for window A (rows 0-2) and B (rows 1-3),
    // sharing the middle-pair min/max. 10 ops per column.
    float alo[6], ami[6], ahi[6];
    float blo[6], bmi[6], bhi[6];
    #pragma unroll
    for (int j = 0; j < 6; ++j) {
        const float mn = fminf(v[1][j], v[2][j]);
        const float mx = fmaxf(v[1][j], v[2][j]);
        const float a = v[0][j];
        const float u = fmaxf(a, mn);
        alo[j] = fminf(a, mn);
        ami[j] = fminf(u, mx);
        ahi[j] = fmaxf(u, mx);
        const float d = v[3][j];
        const float w = fmaxf(d, mn);
        blo[j] = fminf(d, mn);
        bmi[j] = fminf(w, mx);
        bhi[j] = fmaxf(w, mx);
    }

    // Merge: med9 = med3( max3(lows), med3(mids), min3(highs) )
    float oA[4], oB[4];
    #pragma unroll
    for (int k = 0; k < 4; ++k) {
        oA[k] = med3(max3(alo[k], alo[k + 1], alo[k + 2]),
                     med3(ami[k], ami[k + 1], ami[k + 2]),
                     min3(ahi[k], ahi[k + 1], ahi[k + 2]));
        oB[k] = med3(max3(blo[k], blo[k + 1], blo[k + 2]),
                     med3(bmi[k], bmi[k + 1], bmi[k + 2]),
                     min3(bhi[k], bhi[k + 1], bhi[k + 2]));
    }

    float* __restrict__ rowA = outp + y0 * 512 + x0;
    *reinterpret_cast<float4*>(rowA)       = make_float4(oA[0], oA[1], oA[2], oA[3]);
    *reinterpret_cast<float4*>(rowA + 512) = make_float4(oB[0], oB[1], oB[2], oB[3]);
}

__global__ __launch_bounds__(256, 5)
void MedianBlur_34505767256654_kernel(const float* __restrict__ in,
                                      float* __restrict__ out) {
    const int x0 = (blockIdx.x * 32 + threadIdx.x) * 4;   // 4 cols per thread
    const int y0 = (blockIdx.y * 8 + threadIdx.y) * 2;    // 2 rows per thread
    const int base = blockIdx.z * (512 * 512);            // 24 planes

    const float* __restrict__ p = in + base;
    float* __restrict__ o = out + base;

    // Only the top and bottom y-blocks touch the vertical border.
    if (blockIdx.y != 0 && blockIdx.y != 31) {
        tile2x4<false>(p, o, x0, y0);
    } else {
        tile2x4<true>(p, o, x0, y0);
    }
}

extern "C" void kernel_launch(void* const* d_in, const int* in_sizes, int n_in,
                              void* d_out, int out_size) {
    (void)in_sizes; (void)n_in; (void)out_size;
    const float* x = (const float*)d_in[0];
    float* out = (float*)d_out;

    dim3 block(32, 8, 1);                    // 256 threads, tile 128x16 per block
    dim3 grid(512 / 128, 512 / 16, 24);      // (4, 32, 24) = 3072 blocks
    MedianBlur_34505767256654_kernel<<<grid, block>>>(x, out);
}

// round 8
// speedup vs baseline: 1.1775x; 1.0200x over previous
#include <cuda_runtime.h>

// 3x3 median blur, zero padding, fp32 NCHW (8,3,512,512).
// 2 rows x 4 cols per thread; shared vertical pair-sort per column.
// Two-phase body (window A: compute+merge+store, then window B) cuts peak
// register pressure to fit 42 regs -> 6 blocks/SM -> 75% occupancy, while
// keeping each phase fully unrolled (6 independent columns of ILP).

__device__ __forceinline__ float med3(float a, float b, float c) {
    return fmaxf(fminf(a, b), fminf(fmaxf(a, b), c));
}
__device__ __forceinline__ float max3(float a, float b, float c) {
    return fmaxf(fmaxf(a, b), c);
}
__device__ __forceinline__ float min3(float a, float b, float c) {
    return fminf(fminf(a, b), c);
}

template <bool CHECK_Y>
__device__ __forceinline__ void tile2x4(const float* __restrict__ p,
                                        float* __restrict__ outp,
                                        int x0, int y0) {
    // Input window: rows y0-1 .. y0+2, cols x0-1 .. x0+4 (zero-padded).
    float v[4][6];
    const bool lx = (x0 > 0);
    const bool rx = (x0 + 4 < 512);

    #pragma unroll
    for (int i = 0; i < 4; ++i) {
        const int yy = y0 - 1 + i;
        if (CHECK_Y && (unsigned)yy >= 512u) {
            #pragma unroll
            for (int j = 0; j < 6; ++j) v[i][j] = 0.0f;
        } else {
            const float* __restrict__ row = p + yy * 512;
            const float4 a = *reinterpret_cast<const float4*>(row + x0);
            v[i][1] = a.x; v[i][2] = a.y; v[i][3] = a.z; v[i][4] = a.w;
            v[i][0] = lx ? row[x0 - 1] : 0.0f;
            v[i][5] = rx ? row[x0 + 4] : 0.0f;
        }
    }

    float* __restrict__ rowA = outp + y0 * 512 + x0;

    // ---- Phase 1: middle-pair sort + window A (rows 0-2) ----
    float mn[6], mx[6];
    float alo[6], ami[6], ahi[6];
    #pragma unroll
    for (int j = 0; j < 6; ++j) {
        mn[j] = fminf(v[1][j], v[2][j]);
        mx[j] = fmaxf(v[1][j], v[2][j]);
        const float a = v[0][j];                 // row 0 consumed here
        const float u = fmaxf(a, mn[j]);
        alo[j] = fminf(a, mn[j]);
        ami[j] = fminf(u, mx[j]);
        ahi[j] = fmaxf(u, mx[j]);
    }
    {
        float oA[4];
        #pragma unroll
        for (int k = 0; k < 4; ++k) {
            oA[k] = med3(max3(alo[k], alo[k + 1], alo[k + 2]),
                         med3(ami[k], ami[k + 1], ami[k + 2]),
                         min3(ahi[k], ahi[k + 1], ahi[k + 2]));
        }
        *reinterpret_cast<float4*>(rowA) = make_float4(oA[0], oA[1], oA[2], oA[3]);
    }

    // ---- Phase 2: window B (rows 1-3) from retained mn/mx + row 3 ----
    float blo[6], bmi[6], bhi[6];
    #pragma unroll
    for (int j = 0; j < 6; ++j) {
        const float d = v[3][j];
        const float w = fmaxf(d, mn[j]);
        blo[j] = fminf(d, mn[j]);
        bmi[j] = fminf(w, mx[j]);
        bhi[j] = fmaxf(w, mx[j]);
    }
    {
        float oB[4];
        #pragma unroll
        for (int k = 0; k < 4; ++k) {
            oB[k] = med3(max3(blo[k], blo[k + 1], blo[k + 2]),
                         med3(bmi[k], bmi[k + 1], bmi[k + 2]),
                         min3(bhi[k], bhi[k + 1], bhi[k + 2]));
        }
        *reinterpret_cast<float4*>(rowA + 512) = make_float4(oB[0], oB[1], oB[2], oB[3]);
    }
}

__global__ __launch_bounds__(256, 6)
void MedianBlur_34505767256654_kernel(const float* __restrict__ in,
                                      float* __restrict__ out) {
    const int x0 = (blockIdx.x * 32 + threadIdx.x) * 4;   // 4 cols per thread
    const int y0 = (blockIdx.y * 8 + threadIdx.y) * 2;    // 2 rows per thread
    const int base = blockIdx.z * (512 * 512);            // 24 planes

    const float* __restrict__ p = in + base;
    float* __restrict__ o = out + base;

    // Only the top and bottom y-blocks touch the vertical border.
    if (blockIdx.y != 0 && blockIdx.y != 31) {
        tile2x4<false>(p, o, x0, y0);
    } else {
        tile2x4<true>(p, o, x0, y0);
    }
}

extern "C" void kernel_launch(void* const* d_in, const int* in_sizes, int n_in,
                              void* d_out, int out_size) {
    (void)in_sizes; (void)n_in; (void)out_size;
    const float* x = (const float*)d_in[0];
    float* out = (float*)d_out;

    dim3 block(32, 8, 1);                    // 256 threads, tile 128x16 per block
    dim3 grid(512 / 128, 512 / 16, 24);      // (4, 32, 24) = 3072 blocks
    MedianBlur_34505767256654_kernel<<<grid, block>>>(x, out);
}